// round 3
// baseline (speedup 1.0000x reference)
#include <cuda_runtime.h>
#include <mma.h>
#include <math.h>

using namespace nvcuda;

// Problem constants (fixed by setup_inputs)
#define Bb   8
#define Ss   2048
#define Hh   8
#define IDd  256
#define ODd  256
#define KTOT 512              // 2*ID
#define MTOT (Bb*Ss*Hh)       // 131072 tokens
#define BSN  (Bb*Ss)          // 16384 (b,s) pairs

// GEMM tiling
#define BM   64
#define BN   64               // od tile
#define BK   32
#define BKP  36               // padded K stride (bytes mult of 16)
#define CLD  68               // epilogue staging stride

// ---------------- scratch (device globals; no allocation allowed) ----------
__device__ float g_csum[(size_t)MTOT * IDd];   // 128 MB
__device__ float g_f   [(size_t)MTOT * ODd];   // 128 MB
__device__ float g_igh [(size_t)MTOT * ODd];   // 128 MB
__device__ float g_cell[(size_t)MTOT * ODd];   // 128 MB
__device__ float g_mean[BSN];
__device__ float g_rstd[BSN];

// ---------------- K1: cumsum over S per (b,h,d) lane -----------------------
// Latency-bound (16384 lanes only): unroll 16 for MLP.
__global__ void k_cumsum(const float* __restrict__ in) {
    int bh = blockIdx.x;            // 0..63
    int d  = threadIdx.x;           // 0..255
    int b  = bh >> 3, h = bh & 7;
    size_t base   = ((size_t)b * Ss * Hh + h) * IDd + d;
    const size_t stride = (size_t)Hh * IDd;   // 2048
    float acc = 0.f;
    for (int s0 = 0; s0 < Ss; s0 += 16) {
        float v[16];
#pragma unroll
        for (int j = 0; j < 16; j++) v[j] = in[base + (size_t)(s0 + j) * stride];
#pragma unroll
        for (int j = 0; j < 16; j++) {
            acc += v[j];
            g_csum[base + (size_t)(s0 + j) * stride] = acc;
        }
    }
}

// ---------------- K2: per-(b,s) mean/rstd over H*ID=2048 -------------------
__global__ void k_stats() {
    size_t base = (size_t)blockIdx.x * 2048;
    float s1 = 0.f, s2 = 0.f;
    for (int i = threadIdx.x; i < 2048; i += 256) {
        float v = g_csum[base + i];
        s1 += v; s2 += v * v;
    }
#pragma unroll
    for (int o = 16; o; o >>= 1) {
        s1 += __shfl_down_sync(0xffffffffu, s1, o);
        s2 += __shfl_down_sync(0xffffffffu, s2, o);
    }
    __shared__ float a1[8], a2[8];
    int w = threadIdx.x >> 5, l = threadIdx.x & 31;
    if (l == 0) { a1[w] = s1; a2[w] = s2; }
    __syncthreads();
    if (threadIdx.x == 0) {
        float t1 = 0.f, t2 = 0.f;
#pragma unroll
        for (int i = 0; i < 8; i++) { t1 += a1[i]; t2 += a2[i]; }
        float mean = t1 * (1.f / 2048.f);
        float var  = t2 * (1.f / 2048.f) - mean * mean;
        g_mean[blockIdx.x] = mean;
        g_rstd[blockIdx.x] = rsqrtf(var + 1e-6f);
    }
}

__device__ __forceinline__ float sigmoidf_(float x) { return 1.f / (1.f + expf(-x)); }

// ---------------- K3: GEMM1 (3 gates fused) + gate nonlinearities ----------
// g = [input | LN(csum)] @ W_hid^T + b_hid  -> f = sigmoid(g1), igh = sigmoid(g0)*relu(g2)
__global__ void k_gemm1(const float* __restrict__ in,
                        const float* __restrict__ Wh,
                        const float* __restrict__ bhid,
                        const float* __restrict__ lnw,
                        const float* __restrict__ lnb) {
    extern __shared__ float smem[];
    float* As = smem;                    // [BM][BKP]
    float* Bs = smem + BM * BKP;         // [3][BM][BKP]
    float* Cs = smem;                    // alias (epilogue staging) [BM][CLD]
    __shared__ float s_mean[BM], s_rstd[BM];

    const int tid = threadIdx.x;
    const int m0  = blockIdx.x * BM;
    const int n0  = blockIdx.y * BN;

    if (tid < BM) {
        int bs = (m0 + tid) >> 3;
        s_mean[tid] = g_mean[bs];
        s_rstd[tid] = g_rstd[bs];
    }

    const int warp = tid >> 5;
    const int wr = warp >> 2;            // 0..1
    const int wc = warp & 3;             // 0..3

    wmma::fragment<wmma::accumulator, 16, 16, 8, float> acc[2][3];
#pragma unroll
    for (int t = 0; t < 2; t++)
#pragma unroll
        for (int g = 0; g < 3; g++) wmma::fill_fragment(acc[t][g], 0.f);

    const int lr = tid >> 2;             // 0..63 row
    const int lc = (tid & 3) * 8;        // col group
    const int m  = m0 + lr;
    const int hh = m & 7;

    __syncthreads();   // s_mean ready

    for (int kt = 0; kt < KTOT / BK; kt++) {
        const int kk = kt * BK + lc;
        // ---- A tile (build x2 on the fly) ----
        {
            float v[8];
            if (kk < IDd) {
                const float4* p = (const float4*)(in + (size_t)m * IDd + kk);
                float4 x = p[0], y = p[1];
                v[0]=x.x; v[1]=x.y; v[2]=x.z; v[3]=x.w;
                v[4]=y.x; v[5]=y.y; v[6]=y.z; v[7]=y.w;
            } else {
                int d = kk - IDd;
                const float4* p  = (const float4*)(g_csum + (size_t)m * IDd + d);
                const float4* pw = (const float4*)(lnw + hh * IDd + d);
                const float4* pb = (const float4*)(lnb + hh * IDd + d);
                float mu = s_mean[lr], rs = s_rstd[lr];
                float4 x = p[0], y = p[1], wx = pw[0], wy = pw[1], bx = pb[0], by = pb[1];
                v[0]=(x.x-mu)*rs*wx.x+bx.x; v[1]=(x.y-mu)*rs*wx.y+bx.y;
                v[2]=(x.z-mu)*rs*wx.z+bx.z; v[3]=(x.w-mu)*rs*wx.w+bx.w;
                v[4]=(y.x-mu)*rs*wy.x+by.x; v[5]=(y.y-mu)*rs*wy.y+by.y;
                v[6]=(y.z-mu)*rs*wy.z+by.z; v[7]=(y.w-mu)*rs*wy.w+by.w;
            }
#pragma unroll
            for (int j = 0; j < 8; j++) As[lr * BKP + lc + j] = wmma::__float_to_tf32(v[j]);
        }
        // ---- B tiles (3 gates) ----
#pragma unroll
        for (int g = 0; g < 3; g++) {
            int n = g * ODd + n0 + lr;
            const float4* p = (const float4*)(Wh + (size_t)n * KTOT + kk);
            float4 x = p[0], y = p[1];
            float* bsg = Bs + g * BM * BKP + lr * BKP + lc;
            bsg[0]=wmma::__float_to_tf32(x.x); bsg[1]=wmma::__float_to_tf32(x.y);
            bsg[2]=wmma::__float_to_tf32(x.z); bsg[3]=wmma::__float_to_tf32(x.w);
            bsg[4]=wmma::__float_to_tf32(y.x); bsg[5]=wmma::__float_to_tf32(y.y);
            bsg[6]=wmma::__float_to_tf32(y.z); bsg[7]=wmma::__float_to_tf32(y.w);
        }
        __syncthreads();
#pragma unroll
        for (int ks = 0; ks < BK / 8; ks++) {
            wmma::fragment<wmma::matrix_a, 16, 16, 8, wmma::precision::tf32, wmma::row_major> af[2];
            wmma::load_matrix_sync(af[0], As + (wr * 32     ) * BKP + ks * 8, BKP);
            wmma::load_matrix_sync(af[1], As + (wr * 32 + 16) * BKP + ks * 8, BKP);
#pragma unroll
            for (int g = 0; g < 3; g++) {
                wmma::fragment<wmma::matrix_b, 16, 16, 8, wmma::precision::tf32, wmma::col_major> bf;
                wmma::load_matrix_sync(bf, Bs + g * BM * BKP + (wc * 16) * BKP + ks * 8, BKP);
                wmma::mma_sync(acc[0][g], af[0], bf, acc[0][g]);
                wmma::mma_sync(acc[1][g], af[1], bf, acc[1][g]);
            }
        }
        __syncthreads();
    }

    // ---- epilogue: stage each gate through shared, fuse nonlinearities ----
    float igv[16];

    // fgate (gate 1)
#pragma unroll
    for (int t = 0; t < 2; t++)
        wmma::store_matrix_sync(Cs + (wr * 32 + t * 16) * CLD + wc * 16, acc[t][1], CLD, wmma::mem_row_major);
    __syncthreads();
#pragma unroll
    for (int j = 0; j < 16; j++) {
        int e = tid + j * 256, r = e >> 6, c = e & 63;
        float v = Cs[r * CLD + c] + bhid[ODd + n0 + c];
        g_f[(size_t)(m0 + r) * ODd + n0 + c] = sigmoidf_(v);
    }
    __syncthreads();

    // igate (gate 0)
#pragma unroll
    for (int t = 0; t < 2; t++)
        wmma::store_matrix_sync(Cs + (wr * 32 + t * 16) * CLD + wc * 16, acc[t][0], CLD, wmma::mem_row_major);
    __syncthreads();
#pragma unroll
    for (int j = 0; j < 16; j++) {
        int e = tid + j * 256, r = e >> 6, c = e & 63;
        igv[j] = sigmoidf_(Cs[r * CLD + c] + bhid[n0 + c]);
    }
    __syncthreads();

    // hidden (gate 2)
#pragma unroll
    for (int t = 0; t < 2; t++)
        wmma::store_matrix_sync(Cs + (wr * 32 + t * 16) * CLD + wc * 16, acc[t][2], CLD, wmma::mem_row_major);
    __syncthreads();
#pragma unroll
    for (int j = 0; j < 16; j++) {
        int e = tid + j * 256, r = e >> 6, c = e & 63;
        float hv = Cs[r * CLD + c] + bhid[2 * ODd + n0 + c];
        hv = hv > 0.f ? hv : 0.f;
        g_igh[(size_t)(m0 + r) * ODd + n0 + c] = igv[j] * hv;
    }
}

// ---------------- K4: sequential scan over S --------------------------------
// Latency-bound: unroll 16 for MLP.
__global__ void k_scan(const float* __restrict__ init_cx) {
    int lane = blockIdx.x * 256 + threadIdx.x;     // 0..16383
    int od = lane & 255;
    int bh = lane >> 8;
    int h  = bh & 7;
    float c = init_cx[h * ODd + od];
    size_t idx = ((size_t)(bh >> 3) * Ss * Hh + h) * ODd + od;
    const size_t stride = (size_t)Hh * ODd;        // 2048
    for (int s0 = 0; s0 < Ss; s0 += 16) {
        float fv[16], iv[16];
#pragma unroll
        for (int j = 0; j < 16; j++) {
            fv[j] = g_f  [idx + (size_t)j * stride];
            iv[j] = g_igh[idx + (size_t)j * stride];
        }
#pragma unroll
        for (int j = 0; j < 16; j++) {
            c = fv[j] * c + iv[j];
            g_cell[idx + (size_t)j * stride] = c;
        }
        idx += 16 * stride;
    }
}

// ---------------- K5: GEMM2 + output gate epilogue --------------------------
__global__ void k_gemm2(const float* __restrict__ in,
                        const float* __restrict__ Wo,
                        const float* __restrict__ bo,
                        float* __restrict__ out) {
    extern __shared__ float smem[];
    float* As = smem;                    // [BM][BKP]
    float* Bs = smem + BM * BKP;         // [BM][BKP]
    float* Cs = smem;                    // alias [BM][CLD]

    const int tid = threadIdx.x;
    const int m0  = blockIdx.x * BM;
    const int n0  = blockIdx.y * BN;
    const int warp = tid >> 5;
    const int wr = warp >> 2, wc = warp & 3;

    wmma::fragment<wmma::accumulator, 16, 16, 8, float> acc[2];
    wmma::fill_fragment(acc[0], 0.f);
    wmma::fill_fragment(acc[1], 0.f);

    const int lr = tid >> 2;
    const int lc = (tid & 3) * 8;
    const int m  = m0 + lr;

    for (int kt = 0; kt < KTOT / BK; kt++) {
        const int kk = kt * BK + lc;
        {
            const float* src = (kk < IDd) ? (in + (size_t)m * IDd + kk)
                                          : (g_cell + (size_t)m * IDd + (kk - IDd));
            const float4* p = (const float4*)src;
            float4 x = p[0], y = p[1];
            float* as = As + lr * BKP + lc;
            as[0]=wmma::__float_to_tf32(x.x); as[1]=wmma::__float_to_tf32(x.y);
            as[2]=wmma::__float_to_tf32(x.z); as[3]=wmma::__float_to_tf32(x.w);
            as[4]=wmma::__float_to_tf32(y.x); as[5]=wmma::__float_to_tf32(y.y);
            as[6]=wmma::__float_to_tf32(y.z); as[7]=wmma::__float_to_tf32(y.w);
        }
        {
            int n = n0 + lr;
            const float4* p = (const float4*)(Wo + (size_t)n * KTOT + kk);
            float4 x = p[0], y = p[1];
            float* bs = Bs + lr * BKP + lc;
            bs[0]=wmma::__float_to_tf32(x.x); bs[1]=wmma::__float_to_tf32(x.y);
            bs[2]=wmma::__float_to_tf32(x.z); bs[3]=wmma::__float_to_tf32(x.w);
            bs[4]=wmma::__float_to_tf32(y.x); bs[5]=wmma::__float_to_tf32(y.y);
            bs[6]=wmma::__float_to_tf32(y.z); bs[7]=wmma::__float_to_tf32(y.w);
        }
        __syncthreads();
#pragma unroll
        for (int ks = 0; ks < BK / 8; ks++) {
            wmma::fragment<wmma::matrix_a, 16, 16, 8, wmma::precision::tf32, wmma::row_major> af[2];
            wmma::load_matrix_sync(af[0], As + (wr * 32     ) * BKP + ks * 8, BKP);
            wmma::load_matrix_sync(af[1], As + (wr * 32 + 16) * BKP + ks * 8, BKP);
            wmma::fragment<wmma::matrix_b, 16, 16, 8, wmma::precision::tf32, wmma::col_major> bf;
            wmma::load_matrix_sync(bf, Bs + (wc * 16) * BKP + ks * 8, BKP);
            wmma::mma_sync(acc[0], af[0], bf, acc[0]);
            wmma::mma_sync(acc[1], af[1], bf, acc[1]);
        }
        __syncthreads();
    }

#pragma unroll
    for (int t = 0; t < 2; t++)
        wmma::store_matrix_sync(Cs + (wr * 32 + t * 16) * CLD + wc * 16, acc[t], CLD, wmma::mem_row_major);
    __syncthreads();
#pragma unroll
    for (int j = 0; j < 16; j++) {
        int e = tid + j * 256, r = e >> 6, c = e & 63;
        float v = Cs[r * CLD + c] + bo[n0 + c];
        float og = sigmoidf_(v);
        size_t o = (size_t)(m0 + r) * ODd + n0 + c;
        out[o] = og * g_cell[o];
    }
}

// ---------------- launcher ---------------------------------------------------
extern "C" void kernel_launch(void* const* d_in, const int* in_sizes, int n_in,
                              void* d_out, int out_size) {
    const float* in      = (const float*)d_in[0];
    const float* W_hid   = (const float*)d_in[1];
    const float* b_hid   = (const float*)d_in[2];
    const float* W_og    = (const float*)d_in[3];
    const float* b_og    = (const float*)d_in[4];
    const float* ln_w    = (const float*)d_in[5];
    const float* ln_b    = (const float*)d_in[6];
    const float* init_cx = (const float*)d_in[7];
    float* out = (float*)d_out;

    k_cumsum<<<Bb * Hh, 256>>>(in);
    k_stats<<<BSN, 256>>>();

    dim3 g1(MTOT / BM, ODd / BN);
    size_t smem1 = (size_t)(BM * BKP + 3 * BM * BKP) * sizeof(float);   // 36864 B
    k_gemm1<<<g1, 256, smem1>>>(in, W_hid, b_hid, ln_w, ln_b);

    k_scan<<<(Bb * Hh * ODd) / 256, 256>>>(init_cx);

    dim3 g2(MTOT / BM, ODd / BN);
    size_t smem2 = (size_t)(2 * BM * BKP) * sizeof(float);              // 18432 B
    k_gemm2<<<g2, 256, smem2>>>(in, W_og, b_og, out);
}